// round 9
// baseline (speedup 1.0000x reference)
#include <cuda_runtime.h>
#include <cuda_fp16.h>
#include <cstdint>

// Problem constants
#define NUM_PROPERTIES 10000
#define HDIM 512
#define ODIM 2
#define BATCH 512
#define NUM_PROPS 128
#define NROWS (BATCH * NUM_PROPS)   // 65536 (b,p) rows

#define NSM 148
#define CTAS_PER_SM 8
#define GRID_CTAS (NSM * CTAS_PER_SM)            // 1184
#define WARPS_PER_CTA 8
#define TOTAL_WARPS (GRID_CTAS * WARPS_PER_CTA)  // 9472

// fp16 shadow of classifier_weights: (NUM_PROPERTIES, HDIM, 2) as half2 per
// H index -> 10000*512 half2 = 20.48 MB. Static device global (no allocation).
// Rebuilt deterministically on every kernel_launch call.
__device__ __half2 g_w16[NUM_PROPERTIES * HDIM];

// ---------------------------------------------------------------------------
// Conversion: W f32 -> fp16 shadow. Elementwise: half2[i] = cvt(float2[i]).
// Vectorized as float4 -> uint2 (one 16B load, one 8B store per iter).
__global__ __launch_bounds__(256, CTAS_PER_SM)
void convert_w_kernel(const float4* __restrict__ w4) {
    const int n = NUM_PROPERTIES * HDIM * ODIM / 4;   // 2.56M float4
    uint2* __restrict__ dst = (uint2*)g_w16;
    for (int i = blockIdx.x * blockDim.x + threadIdx.x; i < n;
         i += gridDim.x * blockDim.x) {
        const float4 v = w4[i];
        __half2 a = __floats2half2_rn(v.x, v.y);
        __half2 b = __floats2half2_rn(v.z, v.w);
        uint2 o;
        o.x = *reinterpret_cast<const unsigned int*>(&a);
        o.y = *reinterpret_cast<const unsigned int*>(&b);
        dst[i] = o;
    }
}

// ---------------------------------------------------------------------------
__device__ __forceinline__ float2 ldcs_f2(const float2* p) {
    float2 v;
    asm volatile("ld.global.cs.v2.f32 {%0,%1}, [%2];"
                 : "=f"(v.x), "=f"(v.y) : "l"(p));
    return v;
}

// Persistent grid-stride GEMV; one warp per (b,p) row per iteration.
// R9: W read from the fp16 shadow table -> W gather LTS bytes halved
// (268 -> 134 MB). The kernel was at the chip-wide LTS throughput cap
// (~6300 B/cyc); h stays f32 and accumulation stays f32, so only W
// quantization error enters (~3e-4 output rel err, threshold 1e-3).
//
// Dtype self-detection (properties int32 vs int64): warp reads first 256 B
// as int64, ballots range-validity; int32 data passing requires 32
// consecutive odd-index props == 0 (~1e-128). Deterministic.
//
// Per-row layout (wavefront-minimal):
//   lane j = lane + 32k, k = 0..7:
//     h2[j]  : 8B f32 pair (H = 2j, 2j+1), warp-contiguous, .cs streaming
//     w8[j]  : 8B = 2 half2 = W[2j][0..1], W[2j+1][0..1], warp-contiguous
//   -> 32 L1 wavefronts/row (was 48 with f32 W).
__global__ __launch_bounds__(256, CTAS_PER_SM)
void adapter_gemv_kernel(
    const float*  __restrict__ hs,     // (B, P, H)
    const int*    __restrict__ props,  // (B, P) int32 or int64 (detected)
    const float*  __restrict__ mask,   // (B, P)
    const float2* __restrict__ bias,   // (NUM_PROPERTIES, 2) viewed as float2
    float*        __restrict__ out)    // (B, P, 2)
{
    const int lane   = threadIdx.x & 31;
    const int gwarp0 = (blockIdx.x * blockDim.x + threadIdx.x) >> 5;

    // --- per-warp dtype detection (one broadcast 256B window) ---
    const long long* p64 = (const long long*)props;
    long long probe = p64[lane];
    bool in_range = (probe >= 0) && (probe < NUM_PROPERTIES);
    const bool is64 = (__ballot_sync(0xffffffffu, in_range) == 0xffffffffu);

    for (int row = gwarp0; row < NROWS; row += TOTAL_WARPS) {
        long long prop;
        if (is64) prop = p64[row];
        else      prop = (long long)props[row];

        const float2* __restrict__ h2 = (const float2*)(hs + (size_t)row * HDIM);
        const uint2*  __restrict__ w8 = (const uint2*)(g_w16 + (size_t)prop * HDIM);

        float acc0 = 0.0f, acc1 = 0.0f;
        #pragma unroll 4
        for (int k = 0; k < 8; k++) {
            const int j = lane + 32 * k;
            const float2 h = ldcs_f2(&h2[j]);   // streaming: evict-first
            const uint2 wv = w8[j];             // cached: 20MB table lives in L2
            const __half2 ha = *reinterpret_cast<const __half2*>(&wv.x);
            const __half2 hb = *reinterpret_cast<const __half2*>(&wv.y);
            const float2 wa = __half22float2(ha);   // (W[2j][0],   W[2j][1])
            const float2 wb = __half22float2(hb);   // (W[2j+1][0], W[2j+1][1])
            acc0 = fmaf(h.x, wa.x, acc0);
            acc1 = fmaf(h.x, wa.y, acc1);
            acc0 = fmaf(h.y, wb.x, acc0);
            acc1 = fmaf(h.y, wb.y, acc1);
        }

        #pragma unroll
        for (int off = 16; off > 0; off >>= 1) {
            acc0 += __shfl_xor_sync(0xffffffff, acc0, off);
            acc1 += __shfl_xor_sync(0xffffffff, acc1, off);
        }

        if (lane == 0) {
            const float  m = mask[row];
            const float2 b = bias[prop];   // f32 bias: exact
            float2 r;
            r.x = (acc0 + b.x) * m;
            r.y = (acc1 + b.y) * m;
            asm volatile("st.global.cs.v2.f32 [%0], {%1,%2};"
                         :: "l"(((float2*)out) + row), "f"(r.x), "f"(r.y));
        }
    }
}

// ---------------------------------------------------------------------------
extern "C" void kernel_launch(void* const* d_in, const int* in_sizes, int n_in,
                              void* d_out, int out_size) {
    const float*  hs    = (const float*)d_in[0];   // hidden_states (512,128,512) f32
    const int*    props = (const int*)d_in[1];     // properties (512,128)
    const float*  mask  = (const float*)d_in[2];   // mask (512,128) f32
    const float4* W4    = (const float4*)d_in[3];  // classifier_weights (10000,512,2) f32
    const float2* bias  = (const float2*)d_in[4];  // classifier_bias (10000,2) f32
    float*        out   = (float*)d_out;           // (512,128,2) f32

    convert_w_kernel<<<GRID_CTAS, 256>>>(W4);
    adapter_gemv_kernel<<<GRID_CTAS, 256>>>(hs, props, mask, bias, out);
}

// round 11
// speedup vs baseline: 1.4221x; 1.4221x over previous
#include <cuda_runtime.h>
#include <cstdint>

// Problem constants
#define NUM_PROPERTIES 10000
#define HDIM 512
#define ODIM 2
#define BATCH 512
#define NUM_PROPS 128
#define NROWS (BATCH * NUM_PROPS)   // 65536 (b,p) rows

#define NSM 148
#define CTAS_PER_SM 8
#define GRID_CTAS (NSM * CTAS_PER_SM)            // 1184
#define WARPS_PER_CTA 8
#define TOTAL_WARPS (GRID_CTAS * WARPS_PER_CTA)  // 9472

__device__ __forceinline__ float2 ldcs_f2(const float2* p) {
    float2 v;
    asm volatile("ld.global.cs.v2.f32 {%0,%1}, [%2];"
                 : "=f"(v.x), "=f"(v.y) : "l"(p));
    return v;
}

// Persistent grid-stride kernel; one warp per (b,p) row per iteration.
//
// CONVERGED OPTIMUM (best measured 29.18us, reproduced twice). The full
// experiment bracket around this configuration:
//   R1 baseline (8192-CTA, strided W loads)  35.3us
//   R2 +.cs streaming h/out                  33.5us  (DRAM bytes -> floor)
//   R3 +wavefront-minimal lane layout        31.2us  (L1 wf/row 80 -> 48)
//   R4 +persistent grid, fused detection     29.2us  <== this kernel
//   R5 prop-prefetch pipeline                29.4us  (warp pool already hides)
//   R6 property-binned reorder               77.9us  (scatter cost >> reuse)
//   R7 full unroll @ 6 CTAs/SM               33.5us  (occupancy > per-warp MLP)
//   R9 fp16 W shadow (L2 bytes -33%)         41.5us  (bytes NOT binding; ALU up)
// R9 falsified the LTS-cap hypothesis: fewer bytes ran slower. The limiter is
// the latency/queueing structure of stream+gather at full occupancy; every
// structural perturbation measured negative.
//
// Dtype self-detection (properties may be int32 or int64 depending on JAX
// x64 config): every warp reads p64[lane] (first 256 bytes, in-bounds under
// both interpretations) and ballots whether all 32 values lie in
// [0, NUM_PROPERTIES). int32 data passing this requires 32 consecutive
// odd-index props to be zero (~1e-128). Deterministic, identical across warps.
//
// Memory layout per row (wavefront-minimal):
//   W row = 256 float4; lane handles j = lane + 32k, k = 0..7 (contiguous
//   warp-wide, 4 wavefronts/instr); h row = 256 float2 paired 1:1 with W
//   float4s (2 wavefronts/instr).
// hidden_states + out use evict-first (.cs) so the 40 MiB W table stays in L2.
__global__ __launch_bounds__(256, CTAS_PER_SM)
void adapter_gemv_kernel(
    const float*  __restrict__ hs,     // (B, P, H)
    const int*    __restrict__ props,  // (B, P) int32 or int64 (detected)
    const float*  __restrict__ mask,   // (B, P)
    const float*  __restrict__ W,      // (NUM_PROPERTIES, H, 2)
    const float2* __restrict__ bias,   // (NUM_PROPERTIES, 2) viewed as float2
    float*        __restrict__ out)    // (B, P, 2)
{
    const int lane   = threadIdx.x & 31;
    const int gwarp0 = (blockIdx.x * blockDim.x + threadIdx.x) >> 5;

    // --- per-warp dtype detection (one broadcast 256B window) ---
    const long long* p64 = (const long long*)props;
    long long probe = p64[lane];
    bool in_range = (probe >= 0) && (probe < NUM_PROPERTIES);
    const bool is64 = (__ballot_sync(0xffffffffu, in_range) == 0xffffffffu);

    for (int row = gwarp0; row < NROWS; row += TOTAL_WARPS) {
        long long prop;
        if (is64) prop = p64[row];
        else      prop = (long long)props[row];

        const float2* __restrict__ h2 = (const float2*)(hs + (size_t)row * HDIM);
        const float4* __restrict__ w4 = (const float4*)(W + (size_t)prop * (HDIM * ODIM));

        float acc0 = 0.0f, acc1 = 0.0f;
        #pragma unroll 4
        for (int k = 0; k < 8; k++) {
            const int j = lane + 32 * k;
            const float2 h = ldcs_f2(&h2[j]);   // streaming: evict-first
            const float4 w = w4[j];             // default: keep in L2
            acc0 = fmaf(h.x, w.x, acc0);
            acc1 = fmaf(h.x, w.y, acc1);
            acc0 = fmaf(h.y, w.z, acc0);
            acc1 = fmaf(h.y, w.w, acc1);
        }

        #pragma unroll
        for (int off = 16; off > 0; off >>= 1) {
            acc0 += __shfl_xor_sync(0xffffffff, acc0, off);
            acc1 += __shfl_xor_sync(0xffffffff, acc1, off);
        }

        if (lane == 0) {
            const float  m = mask[row];
            const float2 b = bias[prop];   // one aligned 8B load
            float2 r;
            r.x = (acc0 + b.x) * m;
            r.y = (acc1 + b.y) * m;
            asm volatile("st.global.cs.v2.f32 [%0], {%1,%2};"
                         :: "l"(((float2*)out) + row), "f"(r.x), "f"(r.y));
        }
    }
}

extern "C" void kernel_launch(void* const* d_in, const int* in_sizes, int n_in,
                              void* d_out, int out_size) {
    const float*  hs    = (const float*)d_in[0];   // hidden_states (512,128,512) f32
    const int*    props = (const int*)d_in[1];     // properties (512,128)
    const float*  mask  = (const float*)d_in[2];   // mask (512,128) f32
    const float*  W     = (const float*)d_in[3];   // classifier_weights (10000,512,2) f32
    const float2* bias  = (const float2*)d_in[4];  // classifier_bias (10000,2) f32
    float*        out   = (float*)d_out;           // (512,128,2) f32

    adapter_gemv_kernel<<<GRID_CTAS, 256>>>(hs, props, mask, W, bias, out);
}